// round 13
// baseline (speedup 1.0000x reference)
#include <cuda_runtime.h>
#include <cuda_fp16.h>

#define NG 128
#define FEAT 16
#define WIDTH 64
#define NUM_POS 3
#define IN_MLP 25          // FEAT + NUM_POS*3
#define GRID_ELEMS (NG*NG*NG*FEAT)   // 33,554,432

// fp16 copy of the grid: 64 MB -> L2-resident (L2 = 126 MB).
__device__ __half g_grid_h[GRID_ELEMS];

// ---- packed f32x2 helpers (sm_10x) ----
__device__ __forceinline__ unsigned long long pack2(float a, float b) {
    unsigned long long r;
    asm("mov.b64 %0, {%1, %2};" : "=l"(r) : "f"(a), "f"(b));
    return r;
}
__device__ __forceinline__ void unpack2(unsigned long long v, float& a, float& b) {
    asm("mov.b64 {%0, %1}, %2;" : "=f"(a), "=f"(b) : "l"(v));
}
__device__ __forceinline__ unsigned long long fma2(unsigned long long a,
                                                   unsigned long long b,
                                                   unsigned long long c) {
    unsigned long long d;
    asm("fma.rn.f32x2 %0, %1, %2, %3;" : "=l"(d) : "l"(a), "l"(b), "l"(c));
    return d;
}
__device__ __forceinline__ unsigned h2u(__half2 h) {
    return *reinterpret_cast<unsigned*>(&h);
}
__device__ __forceinline__ float redc(float v) {   // reduce over lane bits 1,2
    v += __shfl_xor_sync(0xFFFFFFFFu, v, 2);
    v += __shfl_xor_sync(0xFFFFFFFFu, v, 4);
    return v;
}

__device__ __forceinline__ void cubic_w(float t, float w[4]) {
    float t2 = t * t, t3 = t2 * t;
    w[0] = 0.5f * (-t3 + 2.0f * t2 - t);
    w[1] = 0.5f * (3.0f * t3 - 5.0f * t2 + 2.0f);
    w[2] = 0.5f * (-3.0f * t3 + 4.0f * t2 + t);
    w[3] = 0.5f * (t3 - t2);
}

// ============ grid fp32 -> fp16 convert (streaming, coalesced) ============
__global__ __launch_bounds__(256) void convert_kernel(const float* __restrict__ grid) {
    int i = blockIdx.x * 256 + threadIdx.x;        // i indexes 8-element chunks
    const float4* src = reinterpret_cast<const float4*>(grid) + (size_t)i * 2;
    float4 a = __ldg(src);
    float4 b = __ldg(src + 1);
    uint4 o;
    o.x = h2u(__floats2half2_rn(a.x, a.y));
    o.y = h2u(__floats2half2_rn(a.z, a.w));
    o.z = h2u(__floats2half2_rn(b.x, b.y));
    o.w = h2u(__floats2half2_rn(b.z, b.w));
    reinterpret_cast<uint4*>(g_grid_h)[i] = o;
}

// ============ fused: gather 8 lanes/pt-pair; MLP 4 units x 4 points/lane ====
// Gather (R12 shape): lane sub = (c, fh); 8-lane group g gathers points
// (2g, 2g+1). MLP: lane = (pq = lane>>4, uq = lane&15) covers units
// {uq, uq+16, uq+32, uq+48} x points {4pq..4pq+3}; ONE LDS.128 per input i
// per warp serves all 8 points -> weight wavefronts 12.5/pt.
__global__ __launch_bounds__(256) void fused_kernel(
    const float* __restrict__ x,
    const float* __restrict__ w1,
    const float* __restrict__ b1,
    const float* __restrict__ w2,
    const float* __restrict__ b2,
    float* __restrict__ out,
    int npts)
{
    // s_wu[i][uq] = { pack2(w1[uq][i], w1[uq+16][i]),
    //                 pack2(w1[uq+32][i], w1[uq+48][i]) }
    __shared__ ulonglong2 s_wu[IN_MLP][16];
    __shared__ ulonglong2 s_bu[16];
    __shared__ ulonglong2 s_w2u[16];
    __shared__ float s_b2;

    for (int e = threadIdx.x; e < IN_MLP * 16; e += 256) {
        int i = e >> 4, uq = e & 15;
        ulonglong2 v;
        v.x = pack2(w1[uq * IN_MLP + i],        w1[(uq + 16) * IN_MLP + i]);
        v.y = pack2(w1[(uq + 32) * IN_MLP + i], w1[(uq + 48) * IN_MLP + i]);
        s_wu[i][uq] = v;
    }
    if (threadIdx.x < 16) {
        int uq = threadIdx.x;
        ulonglong2 bv, wv;
        bv.x = pack2(b1[uq],      b1[uq + 16]);
        bv.y = pack2(b1[uq + 32], b1[uq + 48]);
        wv.x = pack2(w2[uq],      w2[uq + 16]);
        wv.y = pack2(w2[uq + 32], w2[uq + 48]);
        s_bu[uq]  = bv;
        s_w2u[uq] = wv;
    }
    if (threadIdx.x == 0) s_b2 = b2[0];
    __syncthreads();

    int warpId = threadIdx.x >> 5;
    int lane   = threadIdx.x & 31;
    // gather roles
    int g      = lane >> 3;          // gather group 0..3
    int sub    = lane & 7;
    int c      = sub >> 1;           // z-tap 0..3
    int fh     = sub & 1;            // feature half 0..1
    int foff   = fh * 8;
    // mlp roles
    int uq     = lane & 15;          // unit quad 0..15
    int pq     = lane >> 4;          // point quad 0..1

    int p_base = blockIdx.x * 64 + warpId * 8;   // this warp's 8 points
    int pg0 = p_base + 2 * g;                    // gather group's two points
    bool glive0 = (pg0 < npts), glive1 = (pg0 + 1 < npts);
    int pc[2];
    pc[0] = glive0 ? pg0 : npts - 1;
    pc[1] = glive1 ? (pg0 + 1) : npts - 1;

    const unsigned m = 0xFFFFFFFFu;
    float4 accA[2], accB[2];
    float ps[2], ps8[2];

    int pk = sub / 3;                 // posenc decomposition of sub (0..7)
    int pd = sub - 3 * pk;
    const float TWO_PI = 6.283185307179586f;

    // -------- gather (fp16 grid), two points sequentially --------
    #pragma unroll
    for (int p = 0; p < 2; p++) {
        int ptc = pc[p];
        float ux = __ldg(&x[3 * ptc + 0]) * 127.0f;
        float uy = __ldg(&x[3 * ptc + 1]) * 127.0f;
        float uz = __ldg(&x[3 * ptc + 2]) * 127.0f;
        float fx = floorf(ux), fy = floorf(uy), fz = floorf(uz);
        float tx = ux - fx, ty = uy - fy, tz = uz - fz;
        int ix0 = (int)fx, iy0 = (int)fy, iz0 = (int)fz;

        float wx[4], wy[4], wz[4];
        cubic_w(tx, wx);
        cubic_w(ty, wy);
        cubic_w(tz, wz);
        float wzc = wz[c];
        int zi = min(max(iz0 + c - 1, 0), NG - 1);

        float4 aA = make_float4(0.f, 0.f, 0.f, 0.f);
        float4 aB = make_float4(0.f, 0.f, 0.f, 0.f);
        #pragma unroll
        for (int a = 0; a < 4; a++) {
            int xi = min(max(ix0 + a - 1, 0), NG - 1);
            const __half* gx = g_grid_h + (size_t)xi * (NG * NG * FEAT);
            float wxa = wx[a];
            #pragma unroll
            for (int b = 0; b < 4; b++) {
                int yi = min(max(iy0 + b - 1, 0), NG - 1);
                float w = wxa * wy[b] * wzc;
                const uint4* gp = reinterpret_cast<const uint4*>(
                    gx + (yi * NG + zi) * FEAT + foff);
                uint4 raw = __ldg(gp);
                float2 f0 = __half22float2(*reinterpret_cast<__half2*>(&raw.x));
                float2 f1 = __half22float2(*reinterpret_cast<__half2*>(&raw.y));
                float2 f2 = __half22float2(*reinterpret_cast<__half2*>(&raw.z));
                float2 f3 = __half22float2(*reinterpret_cast<__half2*>(&raw.w));
                aA.x += w * f0.x;  aA.y += w * f0.y;
                aA.z += w * f1.x;  aA.w += w * f1.y;
                aB.x += w * f2.x;  aB.y += w * f2.y;
                aB.z += w * f3.x;  aB.w += w * f3.y;
            }
        }
        aA.x = redc(aA.x);  aA.y = redc(aA.y);  aA.z = redc(aA.z);  aA.w = redc(aA.w);
        aB.x = redc(aB.x);  aB.y = redc(aB.y);  aB.z = redc(aB.z);  aB.w = redc(aB.w);
        accA[p] = aA;
        accB[p] = aB;

        float t3v = (pd == 0) ? tx : (pd == 1) ? ty : tz;
        ps[p]  = __sinf(TWO_PI * (float)(pk + 1) * t3v);   // sin index 'sub'
        ps8[p] = __sinf(TWO_PI * 3.0f * tz);               // sin index 8
    }
    // lane (g, fh) holds feats fh*8..fh*8+7 of points (2g, 2g+1).

    // -------- MLP: 4 units x 4 points per lane --------
    ulonglong2 bu = s_bu[uq];
    unsigned long long q01[4], q23[4];   // units (uq,uq+16) / (uq+32,uq+48)
    #pragma unroll
    for (int j = 0; j < 4; j++) { q01[j] = bu.x; q23[j] = bu.y; }

    #pragma unroll
    for (int i = 0; i < IN_MLP; i++) {
        ulonglong2 wu = s_wu[i][uq];
        #pragma unroll
        for (int j = 0; j < 4; j++) {
            // this lane's point: p = pq*4 + j; gather group = pq*2 + (j>>1)
            int srcg = (pq << 1) + (j >> 1);
            int pp = j & 1;
            float hv;
            if (i < 16) {
                float v = ((i >> 2) & 1)
                    ? ((i & 3) == 0 ? accB[pp].x : (i & 3) == 1 ? accB[pp].y
                                     : (i & 3) == 2 ? accB[pp].z : accB[pp].w)
                    : ((i & 3) == 0 ? accA[pp].x : (i & 3) == 1 ? accA[pp].y
                                     : (i & 3) == 2 ? accA[pp].z : accA[pp].w);
                hv = __shfl_sync(m, v, srcg * 8 + (i >> 3));
            } else if (i < 24) {
                hv = __shfl_sync(m, ps[pp], srcg * 8 + (i - 16));
            } else {
                hv = __shfl_sync(m, ps8[pp], srcg * 8);
            }
            unsigned long long hp = pack2(hv, hv);
            q01[j] = fma2(wu.x, hp, q01[j]);
            q23[j] = fma2(wu.y, hp, q23[j]);
        }
    }

    // -------- epilogue: swish, w2 dot, reduce over 16 uq lanes --------
    ulonglong2 w2u = s_w2u[uq];
    float w2a, w2b, w2c, w2d;
    unpack2(w2u.x, w2a, w2b);
    unpack2(w2u.y, w2c, w2d);

    float l0 = 0.f, l1 = 0.f, l2 = 0.f, l3 = 0.f;
    #pragma unroll
    for (int j = 0; j < 4; j++) {
        float s0, s1, s2, s3;
        unpack2(q01[j], s0, s1);
        unpack2(q23[j], s2, s3);
        float r0 = s0 * __fdividef(1.0f, 1.0f + __expf(-s0));
        float r1 = s1 * __fdividef(1.0f, 1.0f + __expf(-s1));
        float r2 = s2 * __fdividef(1.0f, 1.0f + __expf(-s2));
        float r3 = s3 * __fdividef(1.0f, 1.0f + __expf(-s3));
        float lv = w2a * r0 + w2b * r1 + w2c * r2 + w2d * r3;
        lv += __shfl_xor_sync(m, lv, 1);
        lv += __shfl_xor_sync(m, lv, 2);
        lv += __shfl_xor_sync(m, lv, 4);
        lv += __shfl_xor_sync(m, lv, 8);
        if (j == 0) l0 = lv; else if (j == 1) l1 = lv;
        else if (j == 2) l2 = lv; else l3 = lv;
    }

    if (uq < 4) {
        int pw = p_base + pq * 4 + uq;
        if (pw < npts) {
            float res = (uq == 0) ? l0 : (uq == 1) ? l1 : (uq == 2) ? l2 : l3;
            out[pw] = res + s_b2;
        }
    }
}

extern "C" void kernel_launch(void* const* d_in, const int* in_sizes, int n_in,
                              void* d_out, int out_size) {
    const float* x    = (const float*)d_in[0];
    const float* grid = (const float*)d_in[1];
    const float* w1   = (const float*)d_in[2];
    const float* b1   = (const float*)d_in[3];
    const float* w2   = (const float*)d_in[4];
    const float* b2   = (const float*)d_in[5];
    float* out = (float*)d_out;

    int npts = in_sizes[0] / 3;

    convert_kernel<<<GRID_ELEMS / 8 / 256, 256>>>(grid);  // 16384 blocks

    int blocks = (npts + 63) / 64;   // 64 points per 256-thread block
    fused_kernel<<<blocks, 256>>>(x, w1, b1, w2, b2, out, npts);
}

// round 14
// speedup vs baseline: 1.0098x; 1.0098x over previous
#include <cuda_runtime.h>
#include <cuda_fp16.h>

#define NG 128
#define FEAT 16
#define WIDTH 64
#define NUM_POS 3
#define IN_MLP 25          // FEAT + NUM_POS*3
#define GRID_ELEMS (NG*NG*NG*FEAT)   // 33,554,432

// fp16 copy of the grid: 64 MB -> L2-resident (L2 = 126 MB).
__device__ __half g_grid_h[GRID_ELEMS];

// ---- packed f32x2 helpers (sm_10x) ----
__device__ __forceinline__ unsigned long long pack2(float a, float b) {
    unsigned long long r;
    asm("mov.b64 %0, {%1, %2};" : "=l"(r) : "f"(a), "f"(b));
    return r;
}
__device__ __forceinline__ void unpack2(unsigned long long v, float& a, float& b) {
    asm("mov.b64 {%0, %1}, %2;" : "=f"(a), "=f"(b) : "l"(v));
}
__device__ __forceinline__ unsigned long long fma2(unsigned long long a,
                                                   unsigned long long b,
                                                   unsigned long long c) {
    unsigned long long d;
    asm("fma.rn.f32x2 %0, %1, %2, %3;" : "=l"(d) : "l"(a), "l"(b), "l"(c));
    return d;
}
__device__ __forceinline__ unsigned long long add2(unsigned long long a,
                                                   unsigned long long b) {
    unsigned long long d;
    asm("add.rn.f32x2 %0, %1, %2;" : "=l"(d) : "l"(a), "l"(b));
    return d;
}
__device__ __forceinline__ unsigned h2u(__half2 h) {
    return *reinterpret_cast<unsigned*>(&h);
}
// packed reduce over lane bits 1,2 (64-bit shfl + packed add)
__device__ __forceinline__ unsigned long long redc2(unsigned long long v) {
    v = add2(v, __shfl_xor_sync(0xFFFFFFFFu, v, 2));
    v = add2(v, __shfl_xor_sync(0xFFFFFFFFu, v, 4));
    return v;
}

__device__ __forceinline__ void cubic_w(float t, float w[4]) {
    float t2 = t * t, t3 = t2 * t;
    w[0] = 0.5f * (-t3 + 2.0f * t2 - t);
    w[1] = 0.5f * (3.0f * t3 - 5.0f * t2 + 2.0f);
    w[2] = 0.5f * (-3.0f * t3 + 4.0f * t2 + t);
    w[3] = 0.5f * (t3 - t2);
}

// ============ grid fp32 -> fp16 convert (streaming, coalesced) ============
__global__ __launch_bounds__(256) void convert_kernel(const float* __restrict__ grid) {
    int i = blockIdx.x * 256 + threadIdx.x;        // i indexes 8-element chunks
    const float4* src = reinterpret_cast<const float4*>(grid) + (size_t)i * 2;
    float4 a = __ldg(src);
    float4 b = __ldg(src + 1);
    uint4 o;
    o.x = h2u(__floats2half2_rn(a.x, a.y));
    o.y = h2u(__floats2half2_rn(a.z, a.w));
    o.z = h2u(__floats2half2_rn(b.x, b.y));
    o.w = h2u(__floats2half2_rn(b.z, b.w));
    reinterpret_cast<uint4*>(g_grid_h)[i] = o;
}

// ============ fused: gather 8 lanes/pt-pair; MLP 4 units x 4 points/lane ====
// Gather: lane sub = (c, fh); 8-lane group g gathers points (2g, 2g+1), with
// all interpolation arithmetic in packed f32x2 (FFMA2 / packed reduce).
// MLP: lane = (pq, uq) covers units {uq, uq+16, uq+32, uq+48} x points
// {4pq..4pq+3}; ONE LDS.128 per input i per warp serves all 8 points.
__global__ __launch_bounds__(256) void fused_kernel(
    const float* __restrict__ x,
    const float* __restrict__ w1,
    const float* __restrict__ b1,
    const float* __restrict__ w2,
    const float* __restrict__ b2,
    float* __restrict__ out,
    int npts)
{
    __shared__ ulonglong2 s_wu[IN_MLP][16];
    __shared__ ulonglong2 s_bu[16];
    __shared__ ulonglong2 s_w2u[16];
    __shared__ float s_b2;

    for (int e = threadIdx.x; e < IN_MLP * 16; e += 256) {
        int i = e >> 4, uq = e & 15;
        ulonglong2 v;
        v.x = pack2(w1[uq * IN_MLP + i],        w1[(uq + 16) * IN_MLP + i]);
        v.y = pack2(w1[(uq + 32) * IN_MLP + i], w1[(uq + 48) * IN_MLP + i]);
        s_wu[i][uq] = v;
    }
    if (threadIdx.x < 16) {
        int uq = threadIdx.x;
        ulonglong2 bv, wv;
        bv.x = pack2(b1[uq],      b1[uq + 16]);
        bv.y = pack2(b1[uq + 32], b1[uq + 48]);
        wv.x = pack2(w2[uq],      w2[uq + 16]);
        wv.y = pack2(w2[uq + 32], w2[uq + 48]);
        s_bu[uq]  = bv;
        s_w2u[uq] = wv;
    }
    if (threadIdx.x == 0) s_b2 = b2[0];
    __syncthreads();

    int warpId = threadIdx.x >> 5;
    int lane   = threadIdx.x & 31;
    // gather roles
    int g      = lane >> 3;          // gather group 0..3
    int sub    = lane & 7;
    int c      = sub >> 1;           // z-tap 0..3
    int fh     = sub & 1;            // feature half 0..1
    int foff   = fh * 8;
    // mlp roles
    int uq     = lane & 15;          // unit quad 0..15
    int pq     = lane >> 4;          // point quad 0..1

    int p_base = blockIdx.x * 64 + warpId * 8;   // this warp's 8 points
    int pg0 = p_base + 2 * g;                    // gather group's two points
    bool glive0 = (pg0 < npts), glive1 = (pg0 + 1 < npts);
    int pc[2];
    pc[0] = glive0 ? pg0 : npts - 1;
    pc[1] = glive1 ? (pg0 + 1) : npts - 1;

    const unsigned m = 0xFFFFFFFFu;
    float4 accA[2], accB[2];         // unpacked after packed reduction
    float ps[2], ps8[2];

    int pk = sub / 3;                 // posenc decomposition of sub (0..7)
    int pd = sub - 3 * pk;
    const float TWO_PI = 6.283185307179586f;

    // -------- gather (fp16 grid), two points, packed f32x2 math --------
    #pragma unroll
    for (int p = 0; p < 2; p++) {
        int ptc = pc[p];
        float ux = __ldg(&x[3 * ptc + 0]) * 127.0f;
        float uy = __ldg(&x[3 * ptc + 1]) * 127.0f;
        float uz = __ldg(&x[3 * ptc + 2]) * 127.0f;
        float fx = floorf(ux), fy = floorf(uy), fz = floorf(uz);
        float tx = ux - fx, ty = uy - fy, tz = uz - fz;
        int ix0 = (int)fx, iy0 = (int)fy, iz0 = (int)fz;

        float wx[4], wy[4], wz[4];
        cubic_w(tx, wx);
        cubic_w(ty, wy);
        cubic_w(tz, wz);
        float wzc = wz[c];
        int zi = min(max(iz0 + c - 1, 0), NG - 1);

        unsigned long long a01 = 0, a23 = 0, a45 = 0, a67 = 0;
        #pragma unroll
        for (int a = 0; a < 4; a++) {
            int xi = min(max(ix0 + a - 1, 0), NG - 1);
            const __half* gx = g_grid_h + (size_t)xi * (NG * NG * FEAT);
            float wxa = wx[a];
            #pragma unroll
            for (int b = 0; b < 4; b++) {
                int yi = min(max(iy0 + b - 1, 0), NG - 1);
                float w = wxa * wy[b] * wzc;
                unsigned long long wp = pack2(w, w);
                const uint4* gp = reinterpret_cast<const uint4*>(
                    gx + (yi * NG + zi) * FEAT + foff);
                uint4 raw = __ldg(gp);
                float2 f0 = __half22float2(*reinterpret_cast<__half2*>(&raw.x));
                float2 f1 = __half22float2(*reinterpret_cast<__half2*>(&raw.y));
                float2 f2 = __half22float2(*reinterpret_cast<__half2*>(&raw.z));
                float2 f3 = __half22float2(*reinterpret_cast<__half2*>(&raw.w));
                a01 = fma2(wp, pack2(f0.x, f0.y), a01);
                a23 = fma2(wp, pack2(f1.x, f1.y), a23);
                a45 = fma2(wp, pack2(f2.x, f2.y), a45);
                a67 = fma2(wp, pack2(f3.x, f3.y), a67);
            }
        }
        // packed reduce over c (lane bits 1,2), then unpack for MLP shuffles
        a01 = redc2(a01);  a23 = redc2(a23);
        a45 = redc2(a45);  a67 = redc2(a67);
        unpack2(a01, accA[p].x, accA[p].y);
        unpack2(a23, accA[p].z, accA[p].w);
        unpack2(a45, accB[p].x, accB[p].y);
        unpack2(a67, accB[p].z, accB[p].w);

        float t3v = (pd == 0) ? tx : (pd == 1) ? ty : tz;
        ps[p]  = __sinf(TWO_PI * (float)(pk + 1) * t3v);   // sin index 'sub'
        ps8[p] = __sinf(TWO_PI * 3.0f * tz);               // sin index 8
    }
    // lane (g, fh) holds feats fh*8..fh*8+7 of points (2g, 2g+1).

    // -------- MLP: 4 units x 4 points per lane --------
    ulonglong2 bu = s_bu[uq];
    unsigned long long q01[4], q23[4];   // units (uq,uq+16) / (uq+32,uq+48)
    #pragma unroll
    for (int j = 0; j < 4; j++) { q01[j] = bu.x; q23[j] = bu.y; }

    #pragma unroll
    for (int i = 0; i < IN_MLP; i++) {
        ulonglong2 wu = s_wu[i][uq];
        #pragma unroll
        for (int j = 0; j < 4; j++) {
            // this lane's point: p = pq*4 + j; gather group = pq*2 + (j>>1)
            int srcg = (pq << 1) + (j >> 1);
            int pp = j & 1;
            float hv;
            if (i < 16) {
                float v = ((i >> 2) & 1)
                    ? ((i & 3) == 0 ? accB[pp].x : (i & 3) == 1 ? accB[pp].y
                                     : (i & 3) == 2 ? accB[pp].z : accB[pp].w)
                    : ((i & 3) == 0 ? accA[pp].x : (i & 3) == 1 ? accA[pp].y
                                     : (i & 3) == 2 ? accA[pp].z : accA[pp].w);
                hv = __shfl_sync(m, v, srcg * 8 + (i >> 3));
            } else if (i < 24) {
                hv = __shfl_sync(m, ps[pp], srcg * 8 + (i - 16));
            } else {
                hv = __shfl_sync(m, ps8[pp], srcg * 8);
            }
            unsigned long long hp = pack2(hv, hv);
            q01[j] = fma2(wu.x, hp, q01[j]);
            q23[j] = fma2(wu.y, hp, q23[j]);
        }
    }

    // -------- epilogue: swish, w2 dot, reduce over 16 uq lanes --------
    ulonglong2 w2u = s_w2u[uq];
    float w2a, w2b, w2c, w2d;
    unpack2(w2u.x, w2a, w2b);
    unpack2(w2u.y, w2c, w2d);

    float l0 = 0.f, l1 = 0.f, l2 = 0.f, l3 = 0.f;
    #pragma unroll
    for (int j = 0; j < 4; j++) {
        float s0, s1, s2, s3;
        unpack2(q01[j], s0, s1);
        unpack2(q23[j], s2, s3);
        float r0 = s0 * __fdividef(1.0f, 1.0f + __expf(-s0));
        float r1 = s1 * __fdividef(1.0f, 1.0f + __expf(-s1));
        float r2 = s2 * __fdividef(1.0f, 1.0f + __expf(-s2));
        float r3 = s3 * __fdividef(1.0f, 1.0f + __expf(-s3));
        float lv = w2a * r0 + w2b * r1 + w2c * r2 + w2d * r3;
        lv += __shfl_xor_sync(m, lv, 1);
        lv += __shfl_xor_sync(m, lv, 2);
        lv += __shfl_xor_sync(m, lv, 4);
        lv += __shfl_xor_sync(m, lv, 8);
        if (j == 0) l0 = lv; else if (j == 1) l1 = lv;
        else if (j == 2) l2 = lv; else l3 = lv;
    }

    if (uq < 4) {
        int pw = p_base + pq * 4 + uq;
        if (pw < npts) {
            float res = (uq == 0) ? l0 : (uq == 1) ? l1 : (uq == 2) ? l2 : l3;
            out[pw] = res + s_b2;
        }
    }
}

extern "C" void kernel_launch(void* const* d_in, const int* in_sizes, int n_in,
                              void* d_out, int out_size) {
    const float* x    = (const float*)d_in[0];
    const float* grid = (const float*)d_in[1];
    const float* w1   = (const float*)d_in[2];
    const float* b1   = (const float*)d_in[3];
    const float* w2   = (const float*)d_in[4];
    const float* b2   = (const float*)d_in[5];
    float* out = (float*)d_out;

    int npts = in_sizes[0] / 3;

    convert_kernel<<<GRID_ELEMS / 8 / 256, 256>>>(grid);  // 16384 blocks

    int blocks = (npts + 63) / 64;   // 64 points per 256-thread block
    fused_kernel<<<blocks, 256>>>(x, w1, b1, w2, b2, out, npts);
}

// round 15
// speedup vs baseline: 1.0156x; 1.0057x over previous
#include <cuda_runtime.h>
#include <cuda_fp16.h>

#define NG 128
#define FEAT 16
#define WIDTH 64
#define NUM_POS 3
#define IN_MLP 25          // FEAT + NUM_POS*3 (padded to 28 in smem)
#define INP 28             // padded input count (x4-tileable)
#define GRID_ELEMS (NG*NG*NG*FEAT)   // 33,554,432

// fp16 copy of the grid: 64 MB -> L2-resident (L2 = 126 MB).
__device__ __half g_grid_h[GRID_ELEMS];

// ---- packed f32x2 helpers (sm_10x) ----
__device__ __forceinline__ unsigned long long pack2(float a, float b) {
    unsigned long long r;
    asm("mov.b64 %0, {%1, %2};" : "=l"(r) : "f"(a), "f"(b));
    return r;
}
__device__ __forceinline__ void unpack2(unsigned long long v, float& a, float& b) {
    asm("mov.b64 {%0, %1}, %2;" : "=f"(a), "=f"(b) : "l"(v));
}
__device__ __forceinline__ unsigned long long fma2(unsigned long long a,
                                                   unsigned long long b,
                                                   unsigned long long c) {
    unsigned long long d;
    asm("fma.rn.f32x2 %0, %1, %2, %3;" : "=l"(d) : "l"(a), "l"(b), "l"(c));
    return d;
}
__device__ __forceinline__ unsigned long long add2(unsigned long long a,
                                                   unsigned long long b) {
    unsigned long long d;
    asm("add.rn.f32x2 %0, %1, %2;" : "=l"(d) : "l"(a), "l"(b));
    return d;
}
__device__ __forceinline__ unsigned h2u(__half2 h) {
    return *reinterpret_cast<unsigned*>(&h);
}
// packed reduce over lane bits 1,2 (64-bit shfl + packed add)
__device__ __forceinline__ unsigned long long redc2(unsigned long long v) {
    v = add2(v, __shfl_xor_sync(0xFFFFFFFFu, v, 2));
    v = add2(v, __shfl_xor_sync(0xFFFFFFFFu, v, 4));
    return v;
}

__device__ __forceinline__ void cubic_w(float t, float w[4]) {
    float t2 = t * t, t3 = t2 * t;
    w[0] = 0.5f * (-t3 + 2.0f * t2 - t);
    w[1] = 0.5f * (3.0f * t3 - 5.0f * t2 + 2.0f);
    w[2] = 0.5f * (-3.0f * t3 + 4.0f * t2 + t);
    w[3] = 0.5f * (t3 - t2);
}

// ============ grid fp32 -> fp16 convert (streaming, coalesced) ============
__global__ __launch_bounds__(256) void convert_kernel(const float* __restrict__ grid) {
    int i = blockIdx.x * 256 + threadIdx.x;        // i indexes 8-element chunks
    const float4* src = reinterpret_cast<const float4*>(grid) + (size_t)i * 2;
    float4 a = __ldg(src);
    float4 b = __ldg(src + 1);
    uint4 o;
    o.x = h2u(__floats2half2_rn(a.x, a.y));
    o.y = h2u(__floats2half2_rn(a.z, a.w));
    o.z = h2u(__floats2half2_rn(b.x, b.y));
    o.w = h2u(__floats2half2_rn(b.z, b.w));
    reinterpret_cast<uint4*>(g_grid_h)[i] = o;
}

// ============ fused: gather 8 lanes/pt-pair; MLP 4 units x 4 points/lane ====
// Gather: lane sub = (c, fh); group g gathers points (2g, 2g+1); packed f32x2
// math; after reduction, c==0 lanes store h to warp-local smem (regs freed).
// MLP: lane = (pq, uq); h fetched as LDS.128 (4 values/instr, 28 instrs/warp
// instead of 100 shuffles); weights one LDS.128 per padded input per warp.
__global__ __launch_bounds__(256, 5) void fused_kernel(
    const float* __restrict__ x,
    const float* __restrict__ w1,
    const float* __restrict__ b1,
    const float* __restrict__ w2,
    const float* __restrict__ b2,
    float* __restrict__ out,
    int npts)
{
    __shared__ ulonglong2 s_wu[INP][16];                 // padded: rows 25..27 zero
    __shared__ ulonglong2 s_bu[16];
    __shared__ ulonglong2 s_w2u[16];
    __shared__ float s_b2;
    __shared__ __align__(16) float s_h[8][8][INP];       // [warp][pt-in-warp][input]

    for (int e = threadIdx.x; e < INP * 16; e += 256) {
        int i = e >> 4, uq = e & 15;
        ulonglong2 v;
        if (i < IN_MLP) {
            v.x = pack2(w1[uq * IN_MLP + i],        w1[(uq + 16) * IN_MLP + i]);
            v.y = pack2(w1[(uq + 32) * IN_MLP + i], w1[(uq + 48) * IN_MLP + i]);
        } else {
            v.x = 0ull; v.y = 0ull;
        }
        s_wu[i][uq] = v;
    }
    if (threadIdx.x < 16) {
        int uq = threadIdx.x;
        ulonglong2 bv, wv;
        bv.x = pack2(b1[uq],      b1[uq + 16]);
        bv.y = pack2(b1[uq + 32], b1[uq + 48]);
        wv.x = pack2(w2[uq],      w2[uq + 16]);
        wv.y = pack2(w2[uq + 32], w2[uq + 48]);
        s_bu[uq]  = bv;
        s_w2u[uq] = wv;
    }
    if (threadIdx.x == 0) s_b2 = b2[0];
    // zero the h padding slots [25..27] once
    for (int e = threadIdx.x; e < 8 * 8 * 3; e += 256) {
        int w = e / 24, r = e % 24;
        s_h[w][r / 3][IN_MLP + (r % 3)] = 0.0f;
    }
    __syncthreads();

    int warpId = threadIdx.x >> 5;
    int lane   = threadIdx.x & 31;
    // gather roles
    int g      = lane >> 3;          // gather group 0..3
    int sub    = lane & 7;
    int c      = sub >> 1;           // z-tap 0..3
    int fh     = sub & 1;            // feature half 0..1
    int foff   = fh * 8;
    // mlp roles
    int uq     = lane & 15;          // unit quad 0..15
    int pq     = lane >> 4;          // point quad 0..1

    int p_base = blockIdx.x * 64 + warpId * 8;   // this warp's 8 points
    int pg0 = p_base + 2 * g;                    // gather group's two points

    const unsigned m = 0xFFFFFFFFu;
    int pk = sub / 3;                 // posenc decomposition of sub (0..7)
    int pd = sub - 3 * pk;
    const float TWO_PI = 6.283185307179586f;

    // -------- gather (fp16 grid), two points, packed f32x2 math --------
    #pragma unroll
    for (int p = 0; p < 2; p++) {
        int ptp = pg0 + p;
        int ptc = (ptp < npts) ? ptp : npts - 1;
        float ux = __ldg(&x[3 * ptc + 0]) * 127.0f;
        float uy = __ldg(&x[3 * ptc + 1]) * 127.0f;
        float uz = __ldg(&x[3 * ptc + 2]) * 127.0f;
        float fx = floorf(ux), fy = floorf(uy), fz = floorf(uz);
        float tx = ux - fx, ty = uy - fy, tz = uz - fz;
        int ix0 = (int)fx, iy0 = (int)fy, iz0 = (int)fz;

        float wx[4], wy[4], wz[4];
        cubic_w(tx, wx);
        cubic_w(ty, wy);
        cubic_w(tz, wz);
        float wzc = wz[c];
        int zi = min(max(iz0 + c - 1, 0), NG - 1);

        unsigned long long a01 = 0, a23 = 0, a45 = 0, a67 = 0;
        #pragma unroll
        for (int a = 0; a < 4; a++) {
            int xi = min(max(ix0 + a - 1, 0), NG - 1);
            const __half* gx = g_grid_h + (size_t)xi * (NG * NG * FEAT);
            float wxa = wx[a];
            #pragma unroll
            for (int b = 0; b < 4; b++) {
                int yi = min(max(iy0 + b - 1, 0), NG - 1);
                float w = wxa * wy[b] * wzc;
                unsigned long long wp = pack2(w, w);
                const uint4* gp = reinterpret_cast<const uint4*>(
                    gx + (yi * NG + zi) * FEAT + foff);
                uint4 raw = __ldg(gp);
                float2 f0 = __half22float2(*reinterpret_cast<__half2*>(&raw.x));
                float2 f1 = __half22float2(*reinterpret_cast<__half2*>(&raw.y));
                float2 f2 = __half22float2(*reinterpret_cast<__half2*>(&raw.z));
                float2 f3 = __half22float2(*reinterpret_cast<__half2*>(&raw.w));
                a01 = fma2(wp, pack2(f0.x, f0.y), a01);
                a23 = fma2(wp, pack2(f1.x, f1.y), a23);
                a45 = fma2(wp, pack2(f2.x, f2.y), a45);
                a67 = fma2(wp, pack2(f3.x, f3.y), a67);
            }
        }
        // packed reduce over c (lane bits 1,2)
        a01 = redc2(a01);  a23 = redc2(a23);
        a45 = redc2(a45);  a67 = redc2(a67);

        int pw = 2 * g + p;                    // point slot within warp
        if (sub < 2) {                          // c==0 lanes; sub == fh
            float* row = s_h[warpId][pw];
            ulonglong2 v0, v1;
            v0.x = a01;  v0.y = a23;
            v1.x = a45;  v1.y = a67;
            *reinterpret_cast<ulonglong2*>(&row[sub * 8 + 0]) = v0;
            *reinterpret_cast<ulonglong2*>(&row[sub * 8 + 4]) = v1;
        }
        // posenc: lane sub supplies sin index 'sub'; lane 0 also index 8
        float t3v = (pd == 0) ? tx : (pd == 1) ? ty : tz;
        s_h[warpId][pw][FEAT + sub] = __sinf(TWO_PI * (float)(pk + 1) * t3v);
        if (sub == 0)
            s_h[warpId][pw][FEAT + 8] = __sinf(TWO_PI * 3.0f * tz);
    }
    __syncwarp();

    // -------- MLP: 4 units x 4 points per lane, h via LDS.128 --------
    ulonglong2 bu = s_bu[uq];
    unsigned long long q01[4], q23[4];   // units (uq,uq+16) / (uq+32,uq+48)
    #pragma unroll
    for (int j = 0; j < 4; j++) { q01[j] = bu.x; q23[j] = bu.y; }

    #pragma unroll
    for (int i4 = 0; i4 < INP; i4 += 4) {
        ulonglong2 w0 = s_wu[i4 + 0][uq];
        ulonglong2 wv1 = s_wu[i4 + 1][uq];
        ulonglong2 wv2 = s_wu[i4 + 2][uq];
        ulonglong2 wv3 = s_wu[i4 + 3][uq];
        #pragma unroll
        for (int j = 0; j < 4; j++) {
            float4 hv = *reinterpret_cast<const float4*>(
                &s_h[warpId][pq * 4 + j][i4]);
            unsigned long long h0 = pack2(hv.x, hv.x);
            unsigned long long h1 = pack2(hv.y, hv.y);
            unsigned long long h2p = pack2(hv.z, hv.z);
            unsigned long long h3 = pack2(hv.w, hv.w);
            q01[j] = fma2(w0.x,  h0,  q01[j]);
            q23[j] = fma2(w0.y,  h0,  q23[j]);
            q01[j] = fma2(wv1.x, h1,  q01[j]);
            q23[j] = fma2(wv1.y, h1,  q23[j]);
            q01[j] = fma2(wv2.x, h2p, q01[j]);
            q23[j] = fma2(wv2.y, h2p, q23[j]);
            q01[j] = fma2(wv3.x, h3,  q01[j]);
            q23[j] = fma2(wv3.y, h3,  q23[j]);
        }
    }

    // -------- epilogue: swish, w2 dot, reduce over 16 uq lanes --------
    ulonglong2 w2u = s_w2u[uq];
    float w2a, w2b, w2c, w2d;
    unpack2(w2u.x, w2a, w2b);
    unpack2(w2u.y, w2c, w2d);

    float l0 = 0.f, l1 = 0.f, l2 = 0.f, l3 = 0.f;
    #pragma unroll
    for (int j = 0; j < 4; j++) {
        float s0, s1, s2, s3;
        unpack2(q01[j], s0, s1);
        unpack2(q23[j], s2, s3);
        float r0 = s0 * __fdividef(1.0f, 1.0f + __expf(-s0));
        float r1 = s1 * __fdividef(1.0f, 1.0f + __expf(-s1));
        float r2 = s2 * __fdividef(1.0f, 1.0f + __expf(-s2));
        float r3 = s3 * __fdividef(1.0f, 1.0f + __expf(-s3));
        float lv = w2a * r0 + w2b * r1 + w2c * r2 + w2d * r3;
        lv += __shfl_xor_sync(m, lv, 1);
        lv += __shfl_xor_sync(m, lv, 2);
        lv += __shfl_xor_sync(m, lv, 4);
        lv += __shfl_xor_sync(m, lv, 8);
        if (j == 0) l0 = lv; else if (j == 1) l1 = lv;
        else if (j == 2) l2 = lv; else l3 = lv;
    }

    if (uq < 4) {
        int pw = p_base + pq * 4 + uq;
        if (pw < npts) {
            float res = (uq == 0) ? l0 : (uq == 1) ? l1 : (uq == 2) ? l2 : l3;
            out[pw] = res + s_b2;
        }
    }
}

extern "C" void kernel_launch(void* const* d_in, const int* in_sizes, int n_in,
                              void* d_out, int out_size) {
    const float* x    = (const float*)d_in[0];
    const float* grid = (const float*)d_in[1];
    const float* w1   = (const float*)d_in[2];
    const float* b1   = (const float*)d_in[3];
    const float* w2   = (const float*)d_in[4];
    const float* b2   = (const float*)d_in[5];
    float* out = (float*)d_out;

    int npts = in_sizes[0] / 3;

    convert_kernel<<<GRID_ELEMS / 8 / 256, 256>>>(grid);  // 16384 blocks

    int blocks = (npts + 63) / 64;   // 64 points per 256-thread block
    fused_kernel<<<blocks, 256>>>(x, w1, b1, w2, b2, out, npts);
}